// round 7
// baseline (speedup 1.0000x reference)
#include <cuda_runtime.h>
#include <cuda_bf16.h>

// Problem constants (fixed by the reference)
#define HS_N    4096
#define HS_P    10
#define HS_D    17
#define HS_PD   (HS_P * HS_D)   // 170 dot products per sample
#define HS_DIM  300             // embedding dim (75 float4)
#define HS_VEC4 (HS_DIM / 4)    // 75

__device__ __forceinline__ float dot4(float4 a, float4 b) {
    return a.x * b.x + a.y * b.y + a.z * b.z + a.w * b.w;
}

__device__ __forceinline__ void emit(float s, int pos, const int* labels,
                                     float* out, float* target) {
    const float o = 1.0f / (1.0f + expf(-s));
    // Threshold the f32 sigmoid VALUE (matches reference rounding at 0.5).
    const int m = (o >= 0.5f) ? 1 : 0;
    const int l = labels[pos];
    out[pos]    = o;
    target[pos] = (m == l) ? 1.0f : 0.0f;
}

__global__ __launch_bounds__(256)
void skip_gram_hs_kernel(const int*   __restrict__ word_idx,   // [N]
                         const int*   __restrict__ paths,      // [N, P, D]
                         const int*   __restrict__ labels,     // [N, P, D]
                         const float* __restrict__ emb1,       // [VOCAB, DIM]
                         const float* __restrict__ emb2,       // [VOCAB-1, DIM]
                         float*       __restrict__ out,        // [N, P, D] sigmoid
                         float*       __restrict__ target)     // [N, P, D]
{
    const int n    = blockIdx.x;
    const int tid  = threadIdx.x;
    const int warp = tid >> 5;
    const int lane = tid & 31;
    const bool tail = (lane < HS_VEC4 - 64);   // lanes 0..10 own float4 #64..74

    // proj = emb1[word_idx[n]] in registers per lane.
    const int w = __ldg(word_idx + n);
    const float4* __restrict__ prow =
        reinterpret_cast<const float4*>(emb1 + (size_t)w * HS_DIM);
    const float4 p0 = __ldg(prow + lane);
    const float4 p1 = __ldg(prow + lane + 32);
    const float4 p2 = tail ? __ldg(prow + lane + 64) : make_float4(0.f, 0.f, 0.f, 0.f);

    const int base = n * HS_PD;
    const float4 z = make_float4(0.f, 0.f, 0.f, 0.f);

    // 8 warps; warp handles k = warp, warp+8, ... (21-22 dots).
    // Main loop: 4 dot products at a time -> 12 wide loads in flight,
    // 4 interleaved shuffle-reduce chains.
    int k = warp;
    for (; k + 24 < HS_PD; k += 32) {
        const int i0 = __ldg(paths + base + k);
        const int i1 = __ldg(paths + base + k + 8);
        const int i2 = __ldg(paths + base + k + 16);
        const int i3 = __ldg(paths + base + k + 24);
        const float4* __restrict__ r0 = reinterpret_cast<const float4*>(emb2 + (size_t)i0 * HS_DIM);
        const float4* __restrict__ r1 = reinterpret_cast<const float4*>(emb2 + (size_t)i1 * HS_DIM);
        const float4* __restrict__ r2 = reinterpret_cast<const float4*>(emb2 + (size_t)i2 * HS_DIM);
        const float4* __restrict__ r3 = reinterpret_cast<const float4*>(emb2 + (size_t)i3 * HS_DIM);

        // Issue all 12 wide loads before consuming.
        float4 a0 = __ldg(r0 + lane),      a1 = __ldg(r0 + lane + 32);
        float4 b0 = __ldg(r1 + lane),      b1 = __ldg(r1 + lane + 32);
        float4 c0 = __ldg(r2 + lane),      c1 = __ldg(r2 + lane + 32);
        float4 d0 = __ldg(r3 + lane),      d1 = __ldg(r3 + lane + 32);
        float4 a2 = z, b2 = z, c2 = z, d2 = z;
        if (tail) {
            a2 = __ldg(r0 + lane + 64);  b2 = __ldg(r1 + lane + 64);
            c2 = __ldg(r2 + lane + 64);  d2 = __ldg(r3 + lane + 64);
        }

        float s0 = dot4(a0, p0) + dot4(a1, p1) + dot4(a2, p2);
        float s1 = dot4(b0, p0) + dot4(b1, p1) + dot4(b2, p2);
        float s2 = dot4(c0, p0) + dot4(c1, p1) + dot4(c2, p2);
        float s3 = dot4(d0, p0) + dot4(d1, p1) + dot4(d2, p2);

        #pragma unroll
        for (int off = 16; off > 0; off >>= 1) {
            s0 += __shfl_xor_sync(0xffffffffu, s0, off);
            s1 += __shfl_xor_sync(0xffffffffu, s1, off);
            s2 += __shfl_xor_sync(0xffffffffu, s2, off);
            s3 += __shfl_xor_sync(0xffffffffu, s3, off);
        }

        if (lane == 0) {
            emit(s0, base + k,      labels, out, target);
            emit(s1, base + k + 8,  labels, out, target);
            emit(s2, base + k + 16, labels, out, target);
            emit(s3, base + k + 24, labels, out, target);
        }
    }

    // 2-way remainder
    for (; k + 8 < HS_PD; k += 16) {
        const int i0 = __ldg(paths + base + k);
        const int i1 = __ldg(paths + base + k + 8);
        const float4* __restrict__ r0 = reinterpret_cast<const float4*>(emb2 + (size_t)i0 * HS_DIM);
        const float4* __restrict__ r1 = reinterpret_cast<const float4*>(emb2 + (size_t)i1 * HS_DIM);

        float4 a0 = __ldg(r0 + lane), a1 = __ldg(r0 + lane + 32);
        float4 b0 = __ldg(r1 + lane), b1 = __ldg(r1 + lane + 32);
        float4 a2 = z, b2 = z;
        if (tail) { a2 = __ldg(r0 + lane + 64); b2 = __ldg(r1 + lane + 64); }

        float s0 = dot4(a0, p0) + dot4(a1, p1) + dot4(a2, p2);
        float s1 = dot4(b0, p0) + dot4(b1, p1) + dot4(b2, p2);

        #pragma unroll
        for (int off = 16; off > 0; off >>= 1) {
            s0 += __shfl_xor_sync(0xffffffffu, s0, off);
            s1 += __shfl_xor_sync(0xffffffffu, s1, off);
        }

        if (lane == 0) {
            emit(s0, base + k,     labels, out, target);
            emit(s1, base + k + 8, labels, out, target);
        }
    }

    // 1-way remainder
    if (k < HS_PD) {
        const int idx = __ldg(paths + base + k);
        const float4* __restrict__ row =
            reinterpret_cast<const float4*>(emb2 + (size_t)idx * HS_DIM);

        float4 a0 = __ldg(row + lane), a1 = __ldg(row + lane + 32);
        float4 a2 = z;
        if (tail) a2 = __ldg(row + lane + 64);

        float s = dot4(a0, p0) + dot4(a1, p1) + dot4(a2, p2);

        #pragma unroll
        for (int off = 16; off > 0; off >>= 1)
            s += __shfl_xor_sync(0xffffffffu, s, off);

        if (lane == 0) emit(s, base + k, labels, out, target);
    }
}

extern "C" void kernel_launch(void* const* d_in, const int* in_sizes, int n_in,
                              void* d_out, int out_size)
{
    // metadata order: word_idx, paths, labels, emb1, emb2
    const int*   word_idx = (const int*)  d_in[0];
    const int*   paths    = (const int*)  d_in[1];
    const int*   labels   = (const int*)  d_in[2];
    const float* emb1     = (const float*)d_in[3];
    const float* emb2     = (const float*)d_in[4];

    float* out    = (float*)d_out;                        // first N*P*D: sigmoid
    float* target = (float*)d_out + (size_t)HS_N * HS_PD; // second N*P*D: target

    skip_gram_hs_kernel<<<HS_N, 256>>>(word_idx, paths, labels, emb1, emb2,
                                       out, target);
}